// round 2
// baseline (speedup 1.0000x reference)
#include <cuda_runtime.h>
#include <math.h>

// Problem constants (fixed by the reference)
#define BB 256
#define VV 128000
#define LL 200
#define NCHUNK 8
#define CHUNK (VV / NCHUNK)      // 16000
#define WORDS (CHUNK / 32)       // 500
#define MAXV 10000.0f

// Scratch: per-row exact integer counters (deterministic accumulation).
__device__ int g_rank[BB];
__device__ int g_masked[BB];

__global__ void zero_kernel() {
    int i = blockIdx.x * blockDim.x + threadIdx.x;
    if (i < BB) { g_rank[i] = 0; g_masked[i] = 0; }
}

__global__ __launch_bounds__(256) void count_kernel(
    const float* __restrict__ scores,
    const int* __restrict__ labels,
    const int* __restrict__ seqs)
{
    __shared__ unsigned int bitmap[WORDS];
    __shared__ int red_rank[8], red_mask[8];

    const int chunk = blockIdx.x;
    const int row   = blockIdx.y;
    const int tid   = threadIdx.x;
    const int lo    = chunk * CHUNK;

    // 1) clear bitmap
    for (int i = tid; i < WORDS; i += blockDim.x) bitmap[i] = 0u;
    __syncthreads();

    // 2) set bits for history items falling inside this chunk
    const int* seq = seqs + row * LL;
    for (int i = tid; i < LL; i += blockDim.x) {
        int v = seq[i];
        unsigned int local = (unsigned int)(v - lo);
        if (local < (unsigned int)CHUNK)
            atomicOr(&bitmap[local >> 5], 1u << (local & 31u));
    }
    __syncthreads();

    // 3) scan this chunk of the row
    const float predict = scores[(size_t)row * VV + labels[row]];
    const float4* __restrict__ p =
        (const float4*)(scores + (size_t)row * VV + lo);

    int rank = 0, masked = 0;
    const int nquads = CHUNK / 4;   // 4000
    for (int i = tid; i < nquads; i += blockDim.x) {
        float4 s = p[i];
        int base = i * 4;
        unsigned int nib = (bitmap[base >> 5] >> (base & 31)) & 0xFu;
        masked += __popc(nib);
        if (!(nib & 1u) && s.x > predict) rank++;
        if (!(nib & 2u) && s.y > predict) rank++;
        if (!(nib & 4u) && s.z > predict) rank++;
        if (!(nib & 8u) && s.w > predict) rank++;
    }

    // 4) block reduction (warp shuffle, then cross-warp)
    unsigned int full = 0xFFFFFFFFu;
    for (int off = 16; off > 0; off >>= 1) {
        rank   += __shfl_down_sync(full, rank, off);
        masked += __shfl_down_sync(full, masked, off);
    }
    int wid = tid >> 5, lid = tid & 31;
    if (lid == 0) { red_rank[wid] = rank; red_mask[wid] = masked; }
    __syncthreads();
    if (tid == 0) {
        int r = 0, m = 0;
        #pragma unroll
        for (int w = 0; w < 8; w++) { r += red_rank[w]; m += red_mask[w]; }
        atomicAdd(&g_rank[row], r);
        atomicAdd(&g_masked[row], m);
    }
}

__global__ __launch_bounds__(256) void finalize_kernel(float* __restrict__ out) {
    const int r = threadIdx.x;   // exactly BB threads
    float rank  = (float)g_rank[r];
    float valid = (float)(VV - g_masked[r]);

    float vals[12];
    const float inv_log = 1.0f / log2f(rank + 2.0f);
    const int ks[5] = {1, 5, 10, 20, 50};
    #pragma unroll
    for (int i = 0; i < 5; i++) {
        float ind = (rank < (float)ks[i]) ? 1.0f : 0.0f;
        vals[2 * i]     = ind * inv_log;  // NDCG@k term
        vals[2 * i + 1] = ind;            // Recall@k term
    }
    vals[10] = 1.0f / (rank + 1.0f);      // MRR term
    vals[11] = 1.0f - rank / valid;       // AUC-like term

    __shared__ float red[BB];
    #pragma unroll
    for (int m = 0; m < 12; m++) {
        red[r] = vals[m];
        __syncthreads();
        for (int s = BB / 2; s > 0; s >>= 1) {
            if (r < s) red[r] += red[r + s];
            __syncthreads();
        }
        if (r == 0) out[m] = red[0] / (float)BB;
        __syncthreads();
    }
    if (r == 0) out[12] = 0.0f;
}

extern "C" void kernel_launch(void* const* d_in, const int* in_sizes, int n_in,
                              void* d_out, int out_size) {
    const float* scores = (const float*)d_in[0];  // [B, V] f32
    const int*   labels = (const int*)d_in[1];    // [B] i32 (JAX x64 disabled)
    const int*   seqs   = (const int*)d_in[2];    // [B, L] i32
    float* out = (float*)d_out;

    zero_kernel<<<1, 256>>>();
    dim3 grid(NCHUNK, BB);
    count_kernel<<<grid, 256>>>(scores, labels, seqs);
    finalize_kernel<<<1, BB>>>(out);
}

// round 4
// speedup vs baseline: 1.1221x; 1.1221x over previous
#include <cuda_runtime.h>
#include <math.h>

#define BB 256
#define VV 128000
#define LL 200
#define NCHUNK 8
#define CHUNK (VV / NCHUNK)      // 16000
#define WORDS (CHUNK / 32)       // 500
#define NBLK (BB * NCHUNK)       // 2048

// Per-(row,chunk) partials: x=rank, y=masked. Every slot written each launch.
__device__ int2 g_part[NBLK];
__device__ unsigned int g_done = 0;   // reset by the last block each launch

__global__ __launch_bounds__(256) void ranker_kernel(
    const float* __restrict__ scores,
    const int* __restrict__ labels,
    const int* __restrict__ seqs,
    float* __restrict__ out)
{
    __shared__ unsigned int bitmap[WORDS];
    __shared__ int red_rank[8], red_mask[8];
    __shared__ int is_last;
    __shared__ float fred[BB];

    const int chunk = blockIdx.x;
    const int row   = blockIdx.y;
    const int tid   = threadIdx.x;
    const int lo    = chunk * CHUNK;

    // 1) clear bitmap
    for (int i = tid; i < WORDS; i += 256) bitmap[i] = 0u;
    __syncthreads();

    // 2) mark history items in this chunk
    const int* seq = seqs + row * LL;
    if (tid < LL) {
        int v = seq[tid];
        unsigned int local = (unsigned int)(v - lo);
        if (local < (unsigned int)CHUNK)
            atomicOr(&bitmap[local >> 5], 1u << (local & 31u));
    }
    __syncthreads();

    // 3) scan the chunk
    const float predict = scores[(size_t)row * VV + labels[row]];
    const float4* __restrict__ p =
        (const float4*)(scores + (size_t)row * VV + lo);

    int rank = 0, masked = 0;
    const int nquads = CHUNK / 4;   // 4000
    #pragma unroll 4
    for (int i = tid; i < nquads; i += 256) {
        float4 s = p[i];
        int base = i * 4;
        unsigned int nib = (bitmap[base >> 5] >> (base & 31)) & 0xFu;
        masked += __popc(nib);
        if (!(nib & 1u) && s.x > predict) rank++;
        if (!(nib & 2u) && s.y > predict) rank++;
        if (!(nib & 4u) && s.z > predict) rank++;
        if (!(nib & 8u) && s.w > predict) rank++;
    }

    // 4) block reduction
    const unsigned int full = 0xFFFFFFFFu;
    for (int off = 16; off > 0; off >>= 1) {
        rank   += __shfl_down_sync(full, rank, off);
        masked += __shfl_down_sync(full, masked, off);
    }
    const int wid = tid >> 5, lid = tid & 31;
    if (lid == 0) { red_rank[wid] = rank; red_mask[wid] = masked; }
    __syncthreads();

    // 5) publish partial, detect last block
    if (tid == 0) {
        int r = 0, m = 0;
        #pragma unroll
        for (int w = 0; w < 8; w++) { r += red_rank[w]; m += red_mask[w]; }
        g_part[row * NCHUNK + chunk] = make_int2(r, m);
        __threadfence();
        unsigned int old = atomicAdd(&g_done, 1u);
        is_last = (old == (unsigned int)(NBLK - 1)) ? 1 : 0;
    }
    __syncthreads();
    if (!is_last) return;

    // ── 6) last block: finalize all 13 metrics ──
    __threadfence();
    const int r = tid;                 // one row per thread (BB == 256 threads)
    volatile int2* vp = (volatile int2*)g_part;
    int rk = 0, mk = 0;
    #pragma unroll
    for (int c = 0; c < NCHUNK; c++) {
        int2 pr;
        pr.x = vp[r * NCHUNK + c].x;
        pr.y = vp[r * NCHUNK + c].y;
        rk += pr.x; mk += pr.y;
    }
    float rankf  = (float)rk;
    float valid  = (float)(VV - mk);

    float vals[12];
    const float inv_log = 1.0f / log2f(rankf + 2.0f);
    const int ks[5] = {1, 5, 10, 20, 50};
    #pragma unroll
    for (int i = 0; i < 5; i++) {
        float ind = (rankf < (float)ks[i]) ? 1.0f : 0.0f;
        vals[2 * i]     = ind * inv_log;
        vals[2 * i + 1] = ind;
    }
    vals[10] = 1.0f / (rankf + 1.0f);
    vals[11] = 1.0f - rankf / valid;

    #pragma unroll
    for (int m = 0; m < 12; m++) {
        fred[r] = vals[m];
        __syncthreads();
        for (int s = BB / 2; s > 0; s >>= 1) {
            if (r < s) fred[r] += fred[r + s];
            __syncthreads();
        }
        if (r == 0) out[m] = fred[0] / (float)BB;
        __syncthreads();
    }
    if (r == 0) {
        out[12] = 0.0f;
        g_done = 0;                    // re-arm for next graph replay
    }
}

extern "C" void kernel_launch(void* const* d_in, const int* in_sizes, int n_in,
                              void* d_out, int out_size) {
    const float* scores = (const float*)d_in[0];  // [B, V] f32
    const int*   labels = (const int*)d_in[1];    // [B] i32
    const int*   seqs   = (const int*)d_in[2];    // [B, L] i32
    float* out = (float*)d_out;

    dim3 grid(NCHUNK, BB);
    ranker_kernel<<<grid, 256>>>(scores, labels, seqs, out);
}